// round 1
// baseline (speedup 1.0000x reference)
#include <cuda_runtime.h>
#include <cuda_bf16.h>
#include <math.h>

#define N_USERS 100000
#define N_ITEMS 50000
#define N_NODES (N_USERS + N_ITEMS)
#define DIM 32
#define N_EDGES 2400000
#define K_STEPS 10

// ---------------- device scratch (no allocations allowed) ----------------
__device__ float g_h[N_NODES * DIM];        // current state
__device__ float g_t[N_NODES * DIM];        // hop-1 result
__device__ float g_init[N_NODES * DIM];     // normalized static state
__device__ float g_alpha[N_NODES];          // sigmoid(alpha_logit)
__device__ int2  g_edges[N_EDGES];          // CSR payload: {src, w bits} sorted by dst
__device__ int   g_rowstart[N_NODES + 1];   // CSR row pointers (by dst)
__device__ int   g_cursor[N_NODES];         // counts, then scatter cursors
__device__ unsigned g_maxbits;              // max row sumsq (bit-compare trick)

// ---------------- 1. zero counters ----------------
__global__ void zero_kernel() {
    int i = blockIdx.x * blockDim.x + threadIdx.x;
    if (i < N_NODES) g_cursor[i] = 0;
    if (i == 0) g_maxbits = 0u;
}

// ---------------- 2. max row-norm^2 (warp per node) ----------------
__global__ void norm_kernel(const float* __restrict__ xu, const float* __restrict__ xi) {
    int warp = (blockIdx.x * blockDim.x + threadIdx.x) >> 5;
    int lane = threadIdx.x & 31;
    if (warp >= N_NODES) return;
    const float* row = (warp < N_USERS) ? (xu + (size_t)warp * DIM)
                                        : (xi + (size_t)(warp - N_USERS) * DIM);
    float v = row[lane];
    float ss = v * v;
    #pragma unroll
    for (int d = 16; d; d >>= 1) ss += __shfl_xor_sync(0xFFFFFFFFu, ss, d);
    if (lane == 0) atomicMax(&g_maxbits, __float_as_uint(ss));  // ss >= 0: bit order == float order
}

// ---------------- 3. histogram of edge_dst ----------------
__global__ void count_kernel(const int* __restrict__ edge_dst) {
    int e = blockIdx.x * blockDim.x + threadIdx.x;
    if (e < N_EDGES) atomicAdd(&g_cursor[edge_dst[e]], 1);
}

// ---------------- 4. single-block exclusive scan (shfl-based) ----------------
__global__ void scan_kernel() {
    __shared__ int warp_sums[32];
    __shared__ int s_carry;
    int lane = threadIdx.x & 31, wid = threadIdx.x >> 5;
    if (threadIdx.x == 0) s_carry = 0;
    __syncthreads();
    for (int base = 0; base < N_NODES; base += 1024) {
        int i = base + threadIdx.x;
        int v = (i < N_NODES) ? g_cursor[i] : 0;
        int x = v;
        #pragma unroll
        for (int d = 1; d < 32; d <<= 1) {
            int t = __shfl_up_sync(0xFFFFFFFFu, x, d);
            if (lane >= d) x += t;
        }
        if (lane == 31) warp_sums[wid] = x;
        __syncthreads();
        if (wid == 0) {
            int y = warp_sums[lane];
            #pragma unroll
            for (int d = 1; d < 32; d <<= 1) {
                int t = __shfl_up_sync(0xFFFFFFFFu, y, d);
                if (lane >= d) y += t;
            }
            warp_sums[lane] = y;  // inclusive totals over warps
        }
        __syncthreads();
        int warp_excl = (wid == 0) ? 0 : warp_sums[wid - 1];
        int incl = s_carry + warp_excl + x;
        int excl = incl - v;
        if (i < N_NODES) g_rowstart[i] = excl;
        __syncthreads();
        if (threadIdx.x == 1023) s_carry = incl;
        __syncthreads();
    }
    if (threadIdx.x == 0) g_rowstart[N_NODES] = s_carry;
}

// ---------------- 5. reset cursors = rowstart ----------------
__global__ void reset_cursor_kernel() {
    int i = blockIdx.x * blockDim.x + threadIdx.x;
    if (i < N_NODES) g_cursor[i] = g_rowstart[i];
}

// ---------------- 6. scatter edges into CSR buckets ----------------
__global__ void scatter_kernel(const int* __restrict__ edge_src,
                               const int* __restrict__ edge_dst,
                               const float* __restrict__ edge_w) {
    int e = blockIdx.x * blockDim.x + threadIdx.x;
    if (e >= N_EDGES) return;
    int dst = edge_dst[e];
    int p = atomicAdd(&g_cursor[dst], 1);
    g_edges[p] = make_int2(edge_src[e], __float_as_int(edge_w[e]));
}

// ---------------- 7. normalize state / static, sigmoid alpha ----------------
__global__ void init_kernel(const float* __restrict__ xu, const float* __restrict__ xi,
                            const float* __restrict__ su, const float* __restrict__ si,
                            const float* __restrict__ alpha_logit) {
    int idx = blockIdx.x * blockDim.x + threadIdx.x;
    if (idx < N_NODES * DIM) {
        float scale = 1.0f / sqrtf(__uint_as_float(g_maxbits));
        float s, st;
        if (idx < N_USERS * DIM) { s = xu[idx]; st = su[idx]; }
        else                     { s = xi[idx - N_USERS * DIM]; st = si[idx - N_USERS * DIM]; }
        g_h[idx]    = s  * scale;
        g_init[idx] = st * scale;
    }
    if (idx < N_NODES) {
        g_alpha[idx] = 1.0f / (1.0f + expf(-alpha_logit[idx]));
    }
}

// ---------------- 8. propagation hops (warp per dst node, lane per dim) ----------------
template <bool UPDATE>
__global__ void hop_kernel(const float* __restrict__ in, float* __restrict__ out,
                           const float* __restrict__ dt) {
    int node = (blockIdx.x * blockDim.x + threadIdx.x) >> 5;
    int lane = threadIdx.x & 31;
    if (node >= N_NODES) return;
    int s = __ldg(&g_rowstart[node]);
    int e = __ldg(&g_rowstart[node + 1]);

    float acc0 = 0.0f, acc1 = 0.0f;
    int k = s;
    for (; k + 1 < e; k += 2) {
        int2 e0 = __ldg(&g_edges[k]);
        int2 e1 = __ldg(&g_edges[k + 1]);
        acc0 += __int_as_float(e0.y) * __ldg(&in[(size_t)e0.x * DIM + lane]);
        acc1 += __int_as_float(e1.y) * __ldg(&in[(size_t)e1.x * DIM + lane]);
    }
    if (k < e) {
        int2 e0 = __ldg(&g_edges[k]);
        acc0 += __int_as_float(e0.y) * __ldg(&in[(size_t)e0.x * DIM + lane]);
    }
    float acc = acc0 + acc1;

    size_t oidx = (size_t)node * DIM + lane;
    if (UPDATE) {
        float step = __ldg(dt) * (1.0f / K_STEPS);
        float h = g_h[oidx];
        out[oidx] = h + step * (acc - __ldg(&g_alpha[node]) * h + __ldg(&g_init[oidx]));
    } else {
        out[oidx] = acc;
    }
}

// ---------------- launch ----------------
extern "C" void kernel_launch(void* const* d_in, const int* in_sizes, int n_in,
                              void* d_out, int out_size) {
    const float* xu          = (const float*)d_in[0];
    const float* xi          = (const float*)d_in[1];
    const float* su          = (const float*)d_in[2];
    const float* si          = (const float*)d_in[3];
    const float* edge_w      = (const float*)d_in[4];
    const float* alpha_logit = (const float*)d_in[5];
    const float* dt          = (const float*)d_in[6];
    const int*   edge_src    = (const int*)d_in[7];
    const int*   edge_dst    = (const int*)d_in[8];
    float*       out         = (float*)d_out;

    const int T = 256;
    const int nodeBlocks     = (N_NODES + T - 1) / T;
    const int warpNodeBlocks = (N_NODES * 32 + T - 1) / T;  // warp-per-node
    const int edgeBlocks     = (N_EDGES + T - 1) / T;
    const int elemBlocks     = (N_NODES * DIM + T - 1) / T;

    zero_kernel<<<nodeBlocks, T>>>();
    norm_kernel<<<warpNodeBlocks, T>>>(xu, xi);
    count_kernel<<<edgeBlocks, T>>>(edge_dst);
    scan_kernel<<<1, 1024>>>();
    reset_cursor_kernel<<<nodeBlocks, T>>>();
    scatter_kernel<<<edgeBlocks, T>>>(edge_src, edge_dst, edge_w);
    init_kernel<<<elemBlocks, T>>>(xu, xi, su, si, alpha_logit);

    void* p_h = nullptr; void* p_t = nullptr;
    cudaGetSymbolAddress(&p_h, g_h);
    cudaGetSymbolAddress(&p_t, g_t);
    float* fh = (float*)p_h;
    float* ft = (float*)p_t;

    for (int step = 0; step < K_STEPS; step++) {
        hop_kernel<false><<<warpNodeBlocks, T>>>(fh, ft, dt);
        float* dst2 = (step == K_STEPS - 1) ? out : fh;
        hop_kernel<true><<<warpNodeBlocks, T>>>(ft, dst2, dt);
    }
}

// round 2
// speedup vs baseline: 1.6414x; 1.6414x over previous
#include <cuda_runtime.h>
#include <cuda_bf16.h>
#include <math.h>

#define N_USERS 100000
#define N_ITEMS 50000
#define N_NODES (N_USERS + N_ITEMS)
#define DIM 32
#define N_EDGES 2400000
#define K_STEPS 10

#define SCAN_BLOCK 1024
#define SCAN_NBLOCKS ((N_NODES + SCAN_BLOCK - 1) / SCAN_BLOCK)   // 147

// ---------------- device scratch (no allocations allowed) ----------------
__device__ float g_h[N_NODES * DIM];        // current state
__device__ float g_t[N_NODES * DIM];        // hop-1 result
__device__ float g_init[N_NODES * DIM];     // normalized static state
__device__ float g_alpha[N_NODES];          // sigmoid(alpha_logit)
__device__ int2  g_edges[N_EDGES];          // CSR payload: {src, w bits} grouped by dst
__device__ int   g_rowstart[N_NODES + 1];   // CSR row pointers (by dst)
__device__ int   g_cursor[N_NODES];         // counts, then scatter cursors
__device__ int   g_blocksums[SCAN_NBLOCKS]; // scan partials
__device__ int   g_blockoffs[SCAN_NBLOCKS + 1];
__device__ unsigned g_maxbits;              // max row sumsq (bit-compare trick)

// ---------------- 1. zero counters ----------------
__global__ void zero_kernel() {
    int i = blockIdx.x * blockDim.x + threadIdx.x;
    if (i < N_NODES) g_cursor[i] = 0;
    if (i == 0) g_maxbits = 0u;
}

// ---------------- 2. max row-norm^2 (warp per node) ----------------
__global__ void norm_kernel(const float* __restrict__ xu, const float* __restrict__ xi) {
    int warp = (blockIdx.x * blockDim.x + threadIdx.x) >> 5;
    int lane = threadIdx.x & 31;
    if (warp >= N_NODES) return;
    const float* row = (warp < N_USERS) ? (xu + (size_t)warp * DIM)
                                        : (xi + (size_t)(warp - N_USERS) * DIM);
    float v = row[lane];
    float ss = v * v;
    #pragma unroll
    for (int d = 16; d; d >>= 1) ss += __shfl_xor_sync(0xFFFFFFFFu, ss, d);
    if (lane == 0) atomicMax(&g_maxbits, __float_as_uint(ss));  // ss >= 0: bit order == float order
}

// ---------------- 3. histogram of edge_dst ----------------
__global__ void count_kernel(const int* __restrict__ edge_dst) {
    int e = blockIdx.x * blockDim.x + threadIdx.x;
    if (e < N_EDGES) atomicAdd(&g_cursor[e[edge_dst] * 0 + edge_dst[e]], 1);
}

// ---------------- 4a. per-block scan (147 blocks x 1024) ----------------
__global__ void scanA_kernel() {
    __shared__ int warp_sums[32];
    int i = blockIdx.x * SCAN_BLOCK + threadIdx.x;
    int lane = threadIdx.x & 31, wid = threadIdx.x >> 5;
    int v = (i < N_NODES) ? g_cursor[i] : 0;
    int x = v;
    #pragma unroll
    for (int d = 1; d < 32; d <<= 1) {
        int t = __shfl_up_sync(0xFFFFFFFFu, x, d);
        if (lane >= d) x += t;
    }
    if (lane == 31) warp_sums[wid] = x;
    __syncthreads();
    if (wid == 0) {
        int y = warp_sums[lane];
        #pragma unroll
        for (int d = 1; d < 32; d <<= 1) {
            int t = __shfl_up_sync(0xFFFFFFFFu, y, d);
            if (lane >= d) y += t;
        }
        warp_sums[lane] = y;
    }
    __syncthreads();
    int warp_excl = (wid == 0) ? 0 : warp_sums[wid - 1];
    int incl = warp_excl + x;
    if (i < N_NODES) g_rowstart[i] = incl - v;   // block-local exclusive
    if (threadIdx.x == SCAN_BLOCK - 1) g_blocksums[blockIdx.x] = incl;
}

// ---------------- 4b. scan of 147 block sums (1 block) ----------------
__global__ void scanB_kernel() {
    __shared__ int sh[256];
    int t = threadIdx.x;
    int v = (t < SCAN_NBLOCKS) ? g_blocksums[t] : 0;
    sh[t] = v;
    __syncthreads();
    // Hillis-Steele inclusive
    for (int d = 1; d < 256; d <<= 1) {
        int add = (t >= d) ? sh[t - d] : 0;
        __syncthreads();
        sh[t] += add;
        __syncthreads();
    }
    if (t < SCAN_NBLOCKS) g_blockoffs[t] = sh[t] - v;   // exclusive
    if (t == SCAN_NBLOCKS - 1) g_blockoffs[SCAN_NBLOCKS] = sh[t];  // total
}

// ---------------- 4c. apply offsets, write rowstart + cursor ----------------
__global__ void scanC_kernel() {
    int i = blockIdx.x * blockDim.x + threadIdx.x;
    if (i < N_NODES) {
        int val = g_rowstart[i] + g_blockoffs[i / SCAN_BLOCK];
        g_rowstart[i] = val;
        g_cursor[i]   = val;
    }
    if (i == 0) g_rowstart[N_NODES] = g_blockoffs[SCAN_NBLOCKS];
}

// ---------------- 5. scatter edges into CSR buckets ----------------
__global__ void scatter_kernel(const int* __restrict__ edge_src,
                               const int* __restrict__ edge_dst,
                               const float* __restrict__ edge_w) {
    int e = blockIdx.x * blockDim.x + threadIdx.x;
    if (e >= N_EDGES) return;
    int dst = edge_dst[e];
    int p = atomicAdd(&g_cursor[dst], 1);
    g_edges[p] = make_int2(edge_src[e], __float_as_int(edge_w[e]));
}

// ---------------- 6. normalize state / static, sigmoid alpha ----------------
__global__ void init_kernel(const float* __restrict__ xu, const float* __restrict__ xi,
                            const float* __restrict__ su, const float* __restrict__ si,
                            const float* __restrict__ alpha_logit) {
    int idx = blockIdx.x * blockDim.x + threadIdx.x;
    if (idx < N_NODES * DIM) {
        float scale = rsqrtf(__uint_as_float(g_maxbits));
        float s, st;
        if (idx < N_USERS * DIM) { s = xu[idx]; st = su[idx]; }
        else                     { s = xi[idx - N_USERS * DIM]; st = si[idx - N_USERS * DIM]; }
        g_h[idx]    = s  * scale;
        g_init[idx] = st * scale;
    }
    if (idx < N_NODES) {
        g_alpha[idx] = 1.0f / (1.0f + expf(-alpha_logit[idx]));
    }
}

// ---------------- 7. propagation hop: 2 nodes per warp, float2 per lane ----
// 16 lanes per node; gather LDG.64 serves one 128B row per half-warp.
template <bool UPDATE>
__global__ void hop_kernel(const float2* __restrict__ in, float2* __restrict__ out,
                           const float* __restrict__ dt) {
    int t = blockIdx.x * blockDim.x + threadIdx.x;
    int node = t >> 4;            // half-warp per node
    int sub  = t & 15;            // float2 slot within the 32-dim row
    if (node >= N_NODES) return;
    int s = __ldg(&g_rowstart[node]);
    int e = __ldg(&g_rowstart[node + 1]);

    float ax0 = 0.f, ay0 = 0.f, ax1 = 0.f, ay1 = 0.f;
    int k = s;
    for (; k + 1 < e; k += 2) {
        int2 e0 = __ldg(&g_edges[k]);
        int2 e1 = __ldg(&g_edges[k + 1]);
        float2 v0 = __ldg(&in[e0.x * (DIM / 2) + sub]);
        float2 v1 = __ldg(&in[e1.x * (DIM / 2) + sub]);
        float w0 = __int_as_float(e0.y);
        float w1 = __int_as_float(e1.y);
        ax0 = fmaf(w0, v0.x, ax0); ay0 = fmaf(w0, v0.y, ay0);
        ax1 = fmaf(w1, v1.x, ax1); ay1 = fmaf(w1, v1.y, ay1);
    }
    if (k < e) {
        int2 e0 = __ldg(&g_edges[k]);
        float2 v0 = __ldg(&in[e0.x * (DIM / 2) + sub]);
        float w0 = __int_as_float(e0.y);
        ax0 = fmaf(w0, v0.x, ax0); ay0 = fmaf(w0, v0.y, ay0);
    }
    float accx = ax0 + ax1, accy = ay0 + ay1;

    int oidx = node * (DIM / 2) + sub;
    if (UPDATE) {
        float step = __ldg(dt) * (1.0f / K_STEPS);
        float2 h   = ((const float2*)g_h)[oidx];
        float2 ini = ((const float2*)g_init)[oidx];
        float a    = __ldg(&g_alpha[node]);
        float2 r;
        r.x = h.x + step * (accx - a * h.x + ini.x);
        r.y = h.y + step * (accy - a * h.y + ini.y);
        out[oidx] = r;
    } else {
        float2 r; r.x = accx; r.y = accy;
        out[oidx] = r;
    }
}

// ---------------- launch ----------------
extern "C" void kernel_launch(void* const* d_in, const int* in_sizes, int n_in,
                              void* d_out, int out_size) {
    const float* xu          = (const float*)d_in[0];
    const float* xi          = (const float*)d_in[1];
    const float* su          = (const float*)d_in[2];
    const float* si          = (const float*)d_in[3];
    const float* edge_w      = (const float*)d_in[4];
    const float* alpha_logit = (const float*)d_in[5];
    const float* dt          = (const float*)d_in[6];
    const int*   edge_src    = (const int*)d_in[7];
    const int*   edge_dst    = (const int*)d_in[8];
    float*       out         = (float*)d_out;

    const int T = 256;
    const int nodeBlocks     = (N_NODES + T - 1) / T;
    const int warpNodeBlocks = (N_NODES * 32 + T - 1) / T;   // warp-per-node (norm)
    const int halfNodeBlocks = (N_NODES * 16 + T - 1) / T;   // half-warp-per-node (hops)
    const int edgeBlocks     = (N_EDGES + T - 1) / T;
    const int elemBlocks     = (N_NODES * DIM + T - 1) / T;

    zero_kernel<<<nodeBlocks, T>>>();
    norm_kernel<<<warpNodeBlocks, T>>>(xu, xi);
    count_kernel<<<edgeBlocks, T>>>(edge_dst);
    scanA_kernel<<<SCAN_NBLOCKS, SCAN_BLOCK>>>();
    scanB_kernel<<<1, 256>>>();
    scanC_kernel<<<nodeBlocks, T>>>();
    scatter_kernel<<<edgeBlocks, T>>>(edge_src, edge_dst, edge_w);
    init_kernel<<<elemBlocks, T>>>(xu, xi, su, si, alpha_logit);

    void* p_h = nullptr; void* p_t = nullptr;
    cudaGetSymbolAddress(&p_h, g_h);
    cudaGetSymbolAddress(&p_t, g_t);
    float2* fh = (float2*)p_h;
    float2* ft = (float2*)p_t;

    for (int step = 0; step < K_STEPS; step++) {
        hop_kernel<false><<<halfNodeBlocks, T>>>(fh, ft, dt);
        float2* dst2 = (step == K_STEPS - 1) ? (float2*)out : fh;
        hop_kernel<true><<<halfNodeBlocks, T>>>(ft, dst2, dt);
    }
}